// round 1
// baseline (speedup 1.0000x reference)
#include <cuda_runtime.h>
#include <cuda_bf16.h>
#include <math.h>

// ---------------- problem constants ----------------
#define PB 256      // batch
#define PN 128      // image tokens
#define PD 768      // model dim
#define PE 3        // experts
#define PS 44       // slots used
#define PES 132     // E*S
#define PH 1024     // hidden
#define PMAXS 88    // mu slot dim
#define PM_TOK (PB*PN)          // 32768 rows
#define PM_FFN (PB*PS)          // 11264 rows per expert

// ---------------- scratch buffers (device globals; no allocs) ----------------
__device__ float g_slot_input[PB * 769];
__device__ float g_slot_bias [PB * PD];
__device__ float g_img_n     [PM_TOK * PD];        // 25.2M
__device__ float g_dot       [PM_TOK];
__device__ float g_mu_cat    [PD * PES];
__device__ float g_logits    [PM_TOK * PES];
__device__ float g_dispatch  [PM_TOK * PES];
__device__ float g_combine   [PM_TOK * PES];
__device__ float g_slot_in   [PB * PES * PD];      // 26M
__device__ float g_hbuf      [PB * PES * PH];      // 34.6M
__device__ float g_slot_out  [PB * PES * PD];      // 26M
__device__ float g_cls_h     [PB * 4 * PD];

// ---------------- helpers ----------------
__device__ __forceinline__ float gelu_exact(float x) {
    return 0.5f * x * (1.0f + erff(x * 0.70710678118654752440f));
}

// ---------------- generic tiled SGEMM ----------------
// C[M,N] = A[M,K] @ B[K,N]  (row-major), optional batch via blockIdx.z strides.
// TRANS_A: A is stored (K, M) (used for dispatch^T @ img).
// MAP_ROWS: row m maps to global row (m/44)*132 + z*44 + m%44 for A reads and C
//           writes (expert-sliced view of the (B,132,*) buffers); z = expert.
// EP: epilogue mode.
#define EP_STORE     0
#define EP_BIAS      1
#define EP_BIAS_GELU 2
#define EP_LOGITS    3

#define TBM 64
#define TBN 64
#define TBK 16

template<bool GUARD, bool TRANS_A, bool MAP_ROWS, int EP>
__global__ __launch_bounds__(256)
void sgemm_kernel(const float* __restrict__ A, const float* __restrict__ B,
                  float* __restrict__ C,
                  int M, int N, int K, int lda, int ldb, int ldc,
                  long long sA, long long sB, long long sC,
                  const float* __restrict__ v1,   // per-col bias / attn weights
                  const float* __restrict__ v2,   // per-row dot (logits)
                  const float* __restrict__ scale_ptr,
                  int biasStride)
{
    const int z = blockIdx.z;
    const float* Ab = A + (long long)z * sA;
    const float* Bb = B + (long long)z * sB;
    float*       Cb = C + (long long)z * sC;

    __shared__ float As[TBK][TBM];
    __shared__ float Bs[TBK][TBN];

    const int tid = threadIdx.x;          // 256 threads
    const int tx = tid & 15, ty = tid >> 4;
    const int m0 = blockIdx.x * TBM;
    const int n0 = blockIdx.y * TBN;

    float acc[4][4];
    #pragma unroll
    for (int i = 0; i < 4; i++)
        #pragma unroll
        for (int j = 0; j < 4; j++) acc[i][j] = 0.f;

    // A (non-trans) load mapping: each thread owns one tile row, 4 k's
    const int a_r  = tid >> 2;          // 0..63
    const int a_c4 = (tid & 3) * 4;     // 0,4,8,12
    // trans-A / B load mapping: k-row = tid/16, 4 consecutive cols
    const int t_k  = tid >> 4;          // 0..15
    const int t_c4 = (tid & 15) * 4;    // 0..60

    long long a_row_off = 0;
    if (!TRANS_A) {
        int gm = m0 + a_r;
        int rr = gm;
        if (MAP_ROWS) rr = (gm / 44) * PES + z * PS + (gm % 44);
        a_row_off = (long long)rr * lda;
    }

    const int nk = (K + TBK - 1) / TBK;
    for (int kt = 0; kt < nk; kt++) {
        const int k0 = kt * TBK;
        // ---- load A tile ----
        if (!TRANS_A) {
            if (GUARD) {
                const int gm = m0 + a_r;
                #pragma unroll
                for (int i = 0; i < 4; i++) {
                    const int k = k0 + a_c4 + i;
                    As[a_c4 + i][a_r] = (gm < M && k < K) ? Ab[a_row_off + k] : 0.f;
                }
            } else {
                float4 v = *reinterpret_cast<const float4*>(Ab + a_row_off + k0 + a_c4);
                As[a_c4 + 0][a_r] = v.x; As[a_c4 + 1][a_r] = v.y;
                As[a_c4 + 2][a_r] = v.z; As[a_c4 + 3][a_r] = v.w;
            }
        } else {
            const int gk = k0 + t_k;
            #pragma unroll
            for (int i = 0; i < 4; i++) {
                const int gm = m0 + t_c4 + i;
                As[t_k][t_c4 + i] = (!GUARD || (gk < K && gm < M))
                                    ? Ab[(long long)gk * lda + gm] : 0.f;
            }
        }
        // ---- load B tile ----
        {
            const int gk = k0 + t_k;
            if (GUARD) {
                #pragma unroll
                for (int i = 0; i < 4; i++) {
                    const int gn = n0 + t_c4 + i;
                    Bs[t_k][t_c4 + i] = (gk < K && gn < N)
                                        ? Bb[(long long)gk * ldb + gn] : 0.f;
                }
            } else {
                float4 v = *reinterpret_cast<const float4*>(Bb + (long long)gk * ldb + n0 + t_c4);
                *reinterpret_cast<float4*>(&Bs[t_k][t_c4]) = v;
            }
        }
        __syncthreads();
        #pragma unroll
        for (int k = 0; k < TBK; k++) {
            float4 ra = *reinterpret_cast<const float4*>(&As[k][ty * 4]);
            float4 rb = *reinterpret_cast<const float4*>(&Bs[k][tx * 4]);
            float a_[4] = {ra.x, ra.y, ra.z, ra.w};
            float b_[4] = {rb.x, rb.y, rb.z, rb.w};
            #pragma unroll
            for (int i = 0; i < 4; i++)
                #pragma unroll
                for (int j = 0; j < 4; j++)
                    acc[i][j] += a_[i] * b_[j];
        }
        __syncthreads();
    }

    // ---- epilogue ----
    #pragma unroll
    for (int i = 0; i < 4; i++) {
        const int gm = m0 + ty * 4 + i;
        if (GUARD && gm >= M) continue;
        int rr = gm;
        if (MAP_ROWS) rr = (gm / 44) * PES + z * PS + (gm % 44);
        #pragma unroll
        for (int j = 0; j < 4; j++) {
            const int gn = n0 + tx * 4 + j;
            if (GUARD && gn >= N) continue;
            float v = acc[i][j];
            if (EP == EP_BIAS) {
                v += v1[z * biasStride + gn];
            } else if (EP == EP_BIAS_GELU) {
                v = gelu_exact(v + v1[z * biasStride + gn]);
            } else if (EP == EP_LOGITS) {
                const float w = v1[gm];
                const int sel = (w > 0.7f) ? 0 : ((w >= 0.3f) ? 1 : 2);
                const int e = gn / PS;
                v = (e == sel) ? (scale_ptr[0] * (v + v2[gm])) : 0.f;
            }
            Cb[(long long)rr * ldc + gn] = v;
        }
    }
}

// ---------------- mu rearrange: mu_cat[d*132 + e*44+s] = mu[e,d,s] ----------------
__global__ void k_prep_mu(const float* __restrict__ mu, float* __restrict__ mu_cat) {
    int idx = blockIdx.x * blockDim.x + threadIdx.x;
    if (idx >= PD * PES) return;
    int d = idx / PES, j = idx % PES;
    int e = j / PS, s = j % PS;
    mu_cat[idx] = mu[((long long)e * PD + d) * PMAXS + s];
}

// ---------------- slot_input = [cls, mean(attn)] ----------------
__global__ void k_build_slotinput(const float* __restrict__ x,
                                  const float* __restrict__ attn,
                                  float* __restrict__ si) {
    int b = blockIdx.x;
    int t = threadIdx.x;       // 256
    __shared__ float red[8];
    float s = (t < PN) ? attn[b * PN + t] : 0.f;
    for (int o = 16; o; o >>= 1) s += __shfl_xor_sync(~0u, s, o);
    if ((t & 31) == 0) red[t >> 5] = s;
    __syncthreads();
    const float* cls = x + (long long)b * 129 * PD;
    float* o = si + (long long)b * 769;
    for (int d = t; d < PD; d += 256) o[d] = cls[d];
    if (t == 0) {
        float m = 0.f;
        #pragma unroll
        for (int i = 0; i < 8; i++) m += red[i];
        o[PD] = m * (1.f / (float)PN);
    }
}

// ---------------- LayerNorm + dot(img_n, slot_bias) ----------------
__global__ void k_ln_dot(const float* __restrict__ x,
                         const float* __restrict__ gamma,
                         const float* __restrict__ beta,
                         const float* __restrict__ slot_bias,
                         float* __restrict__ img_n,
                         float* __restrict__ dot) {
    const int m = blockIdx.x;              // 0..32767
    const int b = m >> 7;
    const int n = m & 127;
    const float* row = x + ((long long)b * 129 + 1 + n) * PD;
    const int t = threadIdx.x;             // 256
    const int w = t >> 5, l = t & 31;
    __shared__ float rs[8], rq[8];

    float v[3], s = 0.f, sq = 0.f;
    #pragma unroll
    for (int i = 0; i < 3; i++) {
        v[i] = row[t + i * 256];
        s += v[i];
        sq += v[i] * v[i];
    }
    for (int o = 16; o; o >>= 1) {
        s  += __shfl_xor_sync(~0u, s, o);
        sq += __shfl_xor_sync(~0u, sq, o);
    }
    if (l == 0) { rs[w] = s; rq[w] = sq; }
    __syncthreads();
    float ts = 0.f, tq = 0.f;
    #pragma unroll
    for (int i = 0; i < 8; i++) { ts += rs[i]; tq += rq[i]; }
    const float mean = ts * (1.f / (float)PD);
    const float var  = tq * (1.f / (float)PD) - mean * mean;
    const float inv  = rsqrtf(var + 1e-5f);
    __syncthreads();   // protect rs before reuse

    const float* sb = slot_bias + (long long)b * PD;
    float* orow = img_n + (long long)m * PD;
    float dp = 0.f;
    #pragma unroll
    for (int i = 0; i < 3; i++) {
        const int d = t + i * 256;
        const float y = (v[i] - mean) * inv * gamma[d] + beta[d];
        orow[d] = y;
        dp += y * sb[d];
    }
    for (int o = 16; o; o >>= 1) dp += __shfl_xor_sync(~0u, dp, o);
    if (l == 0) rs[w] = dp;
    __syncthreads();
    if (t == 0) {
        float d2 = 0.f;
        #pragma unroll
        for (int i = 0; i < 8; i++) d2 += rs[i];
        dot[m] = d2;
    }
}

// ---------------- dispatch: softmax over n (per b, e, s) ----------------
__global__ void k_dispatch(const float* __restrict__ logits, float* __restrict__ disp) {
    const int be = blockIdx.x;              // B*E
    const int b = be / PE, e = be % PE;
    __shared__ float tile[PN][PS];
    __shared__ float csum[PS];
    const int t = threadIdx.x;              // 256
    const float* base = logits + (long long)b * PN * PES + e * PS;
    for (int idx = t; idx < PN * PS; idx += 256) {
        const int n = idx / PS, j = idx % PS;
        tile[n][j] = base[(long long)n * PES + j];
    }
    __syncthreads();
    if (t < PS) {
        float mx = -1e30f;
        for (int n = 0; n < PN; n++) mx = fmaxf(mx, tile[n][t]);
        float sm = 0.f;
        for (int n = 0; n < PN; n++) {
            const float ev = expf(tile[n][t] - mx);
            tile[n][t] = ev;
            sm += ev;
        }
        csum[t] = sm;
    }
    __syncthreads();
    float* ob = disp + (long long)b * PN * PES + e * PS;
    for (int idx = t; idx < PN * PS; idx += 256) {
        const int n = idx / PS, j = idx % PS;
        ob[(long long)n * PES + j] = tile[n][j] / csum[j];
    }
}

// ---------------- combine: softmax over 132 slots (per b, n) ----------------
__global__ void k_combine(const float* __restrict__ logits, float* __restrict__ comb) {
    const int row = blockIdx.x * 8 + (threadIdx.x >> 5);
    const int l = threadIdx.x & 31;
    if (row >= PM_TOK) return;
    const float* r = logits + (long long)row * PES;
    float vals[5], mx = -1e30f;
    #pragma unroll
    for (int i = 0; i < 5; i++) {
        const int j = l + i * 32;
        vals[i] = (j < PES) ? r[j] : -1e30f;
        mx = fmaxf(mx, vals[i]);
    }
    for (int o = 16; o; o >>= 1) mx = fmaxf(mx, __shfl_xor_sync(~0u, mx, o));
    float s = 0.f;
    #pragma unroll
    for (int i = 0; i < 5; i++) {
        const int j = l + i * 32;
        if (j < PES) { vals[i] = expf(vals[i] - mx); s += vals[i]; }
    }
    for (int o = 16; o; o >>= 1) s += __shfl_xor_sync(~0u, s, o);
    const float inv = 1.f / s;
    float* o = comb + (long long)row * PES;
    #pragma unroll
    for (int i = 0; i < 5; i++) {
        const int j = l + i * 32;
        if (j < PES) o[j] = vals[i] * inv;
    }
}

// ---------------- launch ----------------
extern "C" void kernel_launch(void* const* d_in, const int* in_sizes, int n_in,
                              void* d_out, int out_size) {
    const float* x      = (const float*)d_in[0];
    const float* attn   = (const float*)d_in[1];
    const float* gamma  = (const float*)d_in[2];
    const float* beta   = (const float*)d_in[3];
    const float* vsg_w  = (const float*)d_in[4];
    const float* vsg_b  = (const float*)d_in[5];
    const float* mu     = (const float*)d_in[6];
    const float* scale  = (const float*)d_in[7];
    const float* w1     = (const float*)d_in[8];
    const float* b1     = (const float*)d_in[9];
    const float* w2     = (const float*)d_in[10];
    const float* b2     = (const float*)d_in[11];
    const float* cw1    = (const float*)d_in[12];
    const float* cb1    = (const float*)d_in[13];
    const float* cw2    = (const float*)d_in[14];
    const float* cb2    = (const float*)d_in[15];
    float* out = (float*)d_out;

    float *p_si, *p_sb, *p_imgn, *p_dot, *p_mu, *p_log, *p_disp, *p_comb;
    float *p_sin, *p_h, *p_sout, *p_clsh;
    cudaGetSymbolAddress((void**)&p_si,   g_slot_input);
    cudaGetSymbolAddress((void**)&p_sb,   g_slot_bias);
    cudaGetSymbolAddress((void**)&p_imgn, g_img_n);
    cudaGetSymbolAddress((void**)&p_dot,  g_dot);
    cudaGetSymbolAddress((void**)&p_mu,   g_mu_cat);
    cudaGetSymbolAddress((void**)&p_log,  g_logits);
    cudaGetSymbolAddress((void**)&p_disp, g_dispatch);
    cudaGetSymbolAddress((void**)&p_comb, g_combine);
    cudaGetSymbolAddress((void**)&p_sin,  g_slot_in);
    cudaGetSymbolAddress((void**)&p_h,    g_hbuf);
    cudaGetSymbolAddress((void**)&p_sout, g_slot_out);
    cudaGetSymbolAddress((void**)&p_clsh, g_cls_h);

    // 1. rearrange mu -> (768, 132)
    k_prep_mu<<<(PD * PES + 255) / 256, 256>>>(mu, p_mu);

    // 2. slot_input = [cls, mean(attn)]
    k_build_slotinput<<<PB, 256>>>(x, attn, p_si);

    // 3. slot_bias = slot_input @ vsg_w + vsg_b   (256,769)@(769,768)
    {
        dim3 g((PB + 63) / 64, (PD + 63) / 64, 1);
        sgemm_kernel<true, false, false, EP_BIAS><<<g, 256>>>(
            p_si, vsg_w, p_sb, PB, PD, 769, 769, PD, PD,
            0, 0, 0, vsg_b, nullptr, nullptr, 0);
    }

    // 4. LayerNorm + per-row dot with slot_bias
    k_ln_dot<<<PM_TOK, 256>>>(x, gamma, beta, p_sb, p_imgn, p_dot);

    // 5. logits = scale*(img_n @ mu_cat + dot) * expert_mask  (32768,768)@(768,132)
    {
        dim3 g((PM_TOK + 63) / 64, (PES + 63) / 64, 1);
        sgemm_kernel<true, false, false, EP_LOGITS><<<g, 256>>>(
            p_imgn, p_mu, p_log, PM_TOK, PES, PD, PD, PES, PES,
            0, 0, 0, attn, p_dot, scale, 0);
    }

    // 6. dispatch softmax over tokens
    k_dispatch<<<PB * PE, 256>>>(p_log, p_disp);

    // 7. combine softmax over slots
    k_combine<<<PM_TOK / 8, 256>>>(p_log, p_comb);

    // 8. slot_in[b] = dispatch[b]^T @ img[b]   (132,128)@(128,768), batched over b
    {
        dim3 g((PES + 63) / 64, (PD + 63) / 64, PB);
        sgemm_kernel<true, true, false, EP_STORE><<<g, 256>>>(
            p_disp, x + PD, p_sin, PES, PD, PN, PES, PD, PD,
            (long long)PN * PES, (long long)129 * PD, (long long)PES * PD,
            nullptr, nullptr, nullptr, 0);
    }

    // 9. FFN layer 1: h = gelu(slot_in_e @ w1[e] + b1[e])  per expert
    {
        dim3 g(PM_FFN / 64, PH / 64, PE);
        sgemm_kernel<false, false, true, EP_BIAS_GELU><<<g, 256>>>(
            p_sin, w1, p_h, PM_FFN, PH, PD, PD, PH, PH,
            0, (long long)PD * PH, 0, b1, nullptr, nullptr, PH);
    }

    // 10. FFN layer 2: slot_out = h @ w2[e] + b2[e]
    {
        dim3 g(PM_FFN / 64, PD / 64, PE);
        sgemm_kernel<false, false, true, EP_BIAS><<<g, 256>>>(
            p_h, w2, p_sout, PM_FFN, PD, PH, PH, PD, PD,
            0, (long long)PH * PD, 0, b2, nullptr, nullptr, PD);
    }

    // 11. img_out[b] = combine[b] @ slot_out[b]  (128,132)@(132,768) -> out rows 1..128
    {
        dim3 g((PN + 63) / 64, (PD + 63) / 64, PB);
        sgemm_kernel<true, false, false, EP_STORE><<<g, 256>>>(
            p_comb, p_sout, out + PD, PN, PD, PES, PES, PD, PD,
            (long long)PN * PES, (long long)PES * PD, (long long)129 * PD,
            nullptr, nullptr, nullptr, 0);
    }

    // 12. cls_h = gelu(cls @ cw1 + cb1)   (256,768)@(768,3072)
    {
        dim3 g(PB / 64, (4 * PD) / 64, 1);
        sgemm_kernel<false, false, false, EP_BIAS_GELU><<<g, 256>>>(
            x, cw1, p_clsh, PB, 4 * PD, PD, 129 * PD, 4 * PD, 4 * PD,
            0, 0, 0, cb1, nullptr, nullptr, 0);
    }

    // 13. cls_out = cls_h @ cw2 + cb2 -> out row 0
    {
        dim3 g(PB / 64, PD / 64, 1);
        sgemm_kernel<false, false, false, EP_BIAS><<<g, 256>>>(
            p_clsh, cw2, out, PB, PD, 4 * PD, 4 * PD, PD, 129 * PD,
            0, 0, 0, cb2, nullptr, nullptr, 0);
    }
}